// round 4
// baseline (speedup 1.0000x reference)
#include <cuda_runtime.h>
#include <cuda_bf16.h>
#include <cstdint>
#include <math.h>

// ---------------- scratch -------------------------------------------------
__device__ float g_q [2048 * 1024];      // box_feats @ Wq^T
__device__ float g_k [2048 * 1024];      // part_feats @ Wk^T
__device__ float g_pw[1024 * 2048];      // pwT = conv_w @ part_feats^T  [GE, P]
__device__ float g_L [2048 * 16 * 1024]; // logits / softmax

// ---------------- helpers -------------------------------------------------
__device__ __forceinline__ uint32_t smem_u32(const void* p) {
    uint32_t a;
    asm("{ .reg .u64 t; cvta.to.shared.u64 t, %1; cvt.u32.u64 %0, t; }"
        : "=r"(a) : "l"(p));
    return a;
}
__device__ __forceinline__ uint32_t pack_bf(float lo, float hi) {
    uint32_t r;
    asm("cvt.rn.bf16x2.f32 %0, %1, %2;" : "=r"(r) : "f"(hi), "f"(lo));
    return r;
}
#define STS64(a, x, y) \
    asm volatile("st.shared.v2.b32 [%0], {%1, %2};" :: "r"(a), "r"(x), "r"(y) : "memory")

__device__ __forceinline__ void ldsm4(uint32_t* r, uint32_t addr) {
    asm volatile("ldmatrix.sync.aligned.m8n8.x4.shared.b16 {%0,%1,%2,%3}, [%4];"
        : "=r"(r[0]), "=r"(r[1]), "=r"(r[2]), "=r"(r[3]) : "r"(addr));
}
__device__ __forceinline__ void mma16816(float* d, const uint32_t* a, const uint32_t* b) {
    asm volatile(
        "mma.sync.aligned.m16n8k16.row.col.f32.bf16.bf16.f32 "
        "{%0,%1,%2,%3}, {%4,%5,%6,%7}, {%8,%9}, {%0,%1,%2,%3};"
        : "+f"(d[0]), "+f"(d[1]), "+f"(d[2]), "+f"(d[3])
        : "r"(a[0]), "r"(a[1]), "r"(a[2]), "r"(a[3]), "r"(b[0]), "r"(b[1]));
}

// ---------------- bf16-split tensor-core GEMM -----------------------------
// C[m,n] = alpha * sum_k A[m,k]*B[n,k] + bias[n]  (fp32 in/out, ~fp32 precision)
// BM=128, BN=64, BK=32 fp32/iter; 8 warps in 4x2 grid, warp tile 32x32.
// SMEM rows 80B (32 bf16 + 16B pad) -> ldmatrix conflict-free. 2 CTAs/SM.
__global__ __launch_bounds__(256, 2) void tgemm64(
    const float* __restrict__ A, const float* __restrict__ B,
    const float* __restrict__ bias, float* __restrict__ C,
    int K, int lda, int ldb, int ldc,
    long long sA1, long long sA2, long long sB1, long long sB2,
    long long sC1, long long sC2, long long sBias2,
    int ngroup, float alpha)
{
    constexpr int A_MAT = 128 * 80;   // one A matrix (hi or lo)
    constexpr int B_MAT = 64 * 80;
    constexpr int BUFSZ = 2 * A_MAT + 2 * B_MAT;  // 30720

    extern __shared__ char smem[];
    const uint32_t sb = smem_u32(smem);

    const int t = threadIdx.x;
    const int wid = t >> 5, lane = t & 31;
    const int wm = wid & 3, wn = wid >> 2;    // 4x2 warp grid

    const int z = blockIdx.z;
    const int bb = z / ngroup;
    const int gg = z - bb * ngroup;
    A += bb * sA1 + gg * sA2;
    B += bb * sB1 + gg * sB2;
    C += bb * sC1 + gg * sC2;
    if (bias) bias += gg * sBias2;

    const int m0 = blockIdx.y * 128;
    const int n0 = blockIdx.x * 64;

    float4 pa[4];   // A prefetch: 128x32 / 256 thr = 4 float4
    float4 pb[2];   // B prefetch: 64x32 / 256 thr = 2 float4

    auto ldgA = [&](int c) {
        const int k0 = c * 32;
#pragma unroll
        for (int r = 0; r < 4; r++) {
            int f = r * 256 + t, row = f >> 3, seg = f & 7;
            pa[r] = *(const float4*)(A + (size_t)(m0 + row) * lda + k0 + seg * 4);
        }
    };
    auto ldgB = [&](int c) {
        const int k0 = c * 32;
#pragma unroll
        for (int r = 0; r < 2; r++) {
            int f = r * 256 + t, row = f >> 3, seg = f & 7;
            pb[r] = *(const float4*)(B + (size_t)(n0 + row) * ldb + k0 + seg * 4);
        }
    };
    auto sts = [&](int buf) {
        const uint32_t base = sb + buf * BUFSZ;
#pragma unroll
        for (int r = 0; r < 4; r++) {
            int f = r * 256 + t, row = f >> 3, seg = f & 7;
            float4 v = pa[r];
            uint32_t h01 = pack_bf(v.x, v.y);
            uint32_t h23 = pack_bf(v.z, v.w);
            float hx = __uint_as_float(h01 << 16);
            float hy = __uint_as_float(h01 & 0xFFFF0000u);
            float hz = __uint_as_float(h23 << 16);
            float hw = __uint_as_float(h23 & 0xFFFF0000u);
            uint32_t l01 = pack_bf(v.x - hx, v.y - hy);
            uint32_t l23 = pack_bf(v.z - hz, v.w - hw);
            uint32_t off = base + row * 80 + seg * 8;
            STS64(off, h01, h23);
            STS64(off + A_MAT, l01, l23);
        }
#pragma unroll
        for (int r = 0; r < 2; r++) {
            int f = r * 256 + t, row = f >> 3, seg = f & 7;
            float4 v = pb[r];
            uint32_t h01 = pack_bf(v.x, v.y);
            uint32_t h23 = pack_bf(v.z, v.w);
            float hx = __uint_as_float(h01 << 16);
            float hy = __uint_as_float(h01 & 0xFFFF0000u);
            float hz = __uint_as_float(h23 << 16);
            float hw = __uint_as_float(h23 & 0xFFFF0000u);
            uint32_t l01 = pack_bf(v.x - hx, v.y - hy);
            uint32_t l23 = pack_bf(v.z - hz, v.w - hw);
            uint32_t off = base + 2 * A_MAT + row * 80 + seg * 8;
            STS64(off, h01, h23);
            STS64(off + B_MAT, l01, l23);
        }
    };

    float acc[2][4][4];
#pragma unroll
    for (int i = 0; i < 2; i++)
#pragma unroll
        for (int j = 0; j < 4; j++)
#pragma unroll
            for (int q = 0; q < 4; q++) acc[i][j][q] = 0.f;

    const uint32_t a_lane = (uint32_t)((lane & 15) * 80 + (lane >> 4) * 16);
    const uint32_t b_lane = (uint32_t)(((lane & 7) + ((lane >> 4) << 3)) * 80
                                       + ((lane >> 3) & 1) * 16);

    auto compute = [&](int buf) {
        const uint32_t base = sb + buf * BUFSZ;
#pragma unroll
        for (int ks = 0; ks < 2; ks++) {
            const uint32_t ko = ks * 32;
            uint32_t Ah[2][4], Al[2][4], Bh[4][2], Bl[4][2];
#pragma unroll
            for (int mb = 0; mb < 2; mb++) {
                uint32_t ad = base + (wm * 32 + mb * 16) * 80 + a_lane + ko;
                ldsm4(Ah[mb], ad);
                ldsm4(Al[mb], ad + A_MAT);
            }
#pragma unroll
            for (int n2 = 0; n2 < 2; n2++) {
                uint32_t bd = base + 2 * A_MAT + (wn * 32 + n2 * 16) * 80 + b_lane + ko;
                ldsm4(&Bh[2 * n2][0], bd);
                ldsm4(&Bl[2 * n2][0], bd + B_MAT);
            }
#pragma unroll
            for (int mb = 0; mb < 2; mb++)
#pragma unroll
                for (int nb = 0; nb < 4; nb++) {
                    mma16816(acc[mb][nb], Ah[mb], Bh[nb]);
                    mma16816(acc[mb][nb], Ah[mb], Bl[nb]);
                    mma16816(acc[mb][nb], Al[mb], Bh[nb]);
                }
        }
    };

    const int NC = K >> 5;
    ldgA(0); ldgB(0);
    sts(0);
    if (NC > 1) { ldgA(1); ldgB(1); }
    __syncthreads();

    // one barrier per iteration:
    // at iter c, pa/pb hold chunk c+1; buffer (c+1)&1 was last read at iter c-1
    // (protected by the barrier ending iter c-1).
    for (int c = 0; c < NC; c++) {
        if (c + 1 < NC) sts((c + 1) & 1);
        if (c + 2 < NC) { ldgA(c + 2); ldgB(c + 2); }
        compute(c & 1);
        __syncthreads();
    }

    // epilogue
    const int er = lane >> 2, ec = (lane & 3) * 2;
#pragma unroll
    for (int mb = 0; mb < 2; mb++) {
#pragma unroll
        for (int nb = 0; nb < 4; nb++) {
            const int m = m0 + wm * 32 + mb * 16 + er;
            const int n = n0 + wn * 32 + nb * 8 + ec;
            float b0 = 0.f, b1 = 0.f;
            if (bias) { b0 = bias[n]; b1 = bias[n + 1]; }
            float2 v0, v1;
            v0.x = alpha * acc[mb][nb][0] + b0;
            v0.y = alpha * acc[mb][nb][1] + b1;
            v1.x = alpha * acc[mb][nb][2] + b0;
            v1.y = alpha * acc[mb][nb][3] + b1;
            *(float2*)(C + (size_t)m * ldc + n) = v0;
            *(float2*)(C + (size_t)(m + 8) * ldc + n) = v1;
        }
    }
}

// ---------------- fused poslogit + softmax --------------------------------
// one block per (n, b): computes pos logits for all 16 groups x 1024 parts,
// adds att (already in L), softmaxes each of the 16 rows, writes back to L.
__global__ __launch_bounds__(256) void fused_ps(
    const float* __restrict__ rois, const float* __restrict__ part_rois,
    const float* __restrict__ Wg_w, const float* __restrict__ Wg_b,
    float* __restrict__ L)
{
    extern __shared__ float fsm[];
    float* sm = fsm;                 // [16][1024]
    float* wg = fsm + 16 * 1024;     // [16][64]
    float* wb = wg + 1024;           // [16]

    const int t = threadIdx.x;
    for (int i = t; i < 1024; i += 256) wg[i] = Wg_w[i];
    if (t < 16) wb[t] = Wg_b[t];

    const int n = blockIdx.x;
    const int b = blockIdx.y;
    const int ng = b * 1024 + n;
    const size_t base = (size_t)ng * 16 * 1024;

    const float xmin = rois[ng * 5 + 1];
    const float ymin = rois[ng * 5 + 2];
    const float xmax = rois[ng * 5 + 3];
    const float ymax = rois[ng * 5 + 4];
    const float bw = xmax - xmin + 1.f;
    const float bh = ymax - ymin + 1.f;
    const float cx = 0.5f * (xmin + xmax);
    const float cy = 0.5f * (ymin + ymax);
    __syncthreads();

    const float inv_em[8] = {
        1.0f, 0.42169651f, 0.17782794f, 0.074989424f,
        0.031622777f, 0.013335215f, 0.0056234133f, 0.0023713737f};

#pragma unroll
    for (int cc = 0; cc < 4; cc++) {
        const int p = cc * 256 + t;
        const int pg = b * 1024 + p;
        const float pxmin = part_rois[pg * 5 + 1];
        const float pymin = part_rois[pg * 5 + 2];
        const float pxmax = part_rois[pg * 5 + 3];
        const float pymax = part_rois[pg * 5 + 4];
        const float pw = pxmax - pxmin + 1.f;
        const float ph = pymax - pymin + 1.f;
        const float pcx = 0.5f * (pxmin + pxmax);
        const float pcy = 0.5f * (pymin + pymax);

        float dx = fabsf((cx - pcx) / bw);
        float dy = fabsf((cy - pcy) / bh);
        dx = logf(fmaxf(dx, 1e-3f));
        dy = logf(fmaxf(dy, 1e-3f));
        const float dw = logf(pw / bw);
        const float dh = logf(ph / bh);
        float pos[4] = {dx, dy, dw, dh};

        float acc[16];
#pragma unroll
        for (int g = 0; g < 16; g++) acc[g] = wb[g];
#pragma unroll
        for (int i = 0; i < 4; i++) {
            const float pv = 100.f * pos[i];
#pragma unroll
            for (int j = 0; j < 8; j++) {
                float s, c;
                __sincosf(pv * inv_em[j], &s, &c);
#pragma unroll
                for (int g = 0; g < 16; g++)
                    acc[g] += s * wg[g * 64 + i * 16 + j]
                            + c * wg[g * 64 + i * 16 + 8 + j];
            }
        }
#pragma unroll
        for (int g = 0; g < 16; g++)
            sm[g * 1024 + p] = L[base + (size_t)g * 1024 + p]
                             + logf(fmaxf(acc[g], 1e-6f));
    }
    __syncthreads();

    // softmax: warp w handles rows g = 2w, 2w+1
    const int w = t >> 5, lane = t & 31;
#pragma unroll
    for (int ggi = 0; ggi < 2; ggi++) {
        const int g = w * 2 + ggi;
        float* row = sm + g * 1024;

        float mx = -1e30f;
#pragma unroll
        for (int i = 0; i < 32; i++) mx = fmaxf(mx, row[i * 32 + lane]);
#pragma unroll
        for (int o = 16; o > 0; o >>= 1)
            mx = fmaxf(mx, __shfl_xor_sync(0xFFFFFFFFu, mx, o));

        float s = 0.f;
#pragma unroll
        for (int i = 0; i < 32; i++) {
            float e = __expf(row[i * 32 + lane] - mx);
            row[i * 32 + lane] = e;
            s += e;
        }
#pragma unroll
        for (int o = 16; o > 0; o >>= 1)
            s += __shfl_xor_sync(0xFFFFFFFFu, s, o);
        const float inv = 1.f / s;

#pragma unroll
        for (int i = 0; i < 32; i++)
            L[base + (size_t)g * 1024 + i * 32 + lane] = row[i * 32 + lane] * inv;
    }
}

// ---------------- host ----------------------------------------------------
extern "C" void kernel_launch(void* const* d_in, const int* in_sizes, int n_in,
                              void* d_out, int out_size)
{
    const float* rois       = (const float*)d_in[0];
    const float* part_rois  = (const float*)d_in[1];
    const float* box_feats  = (const float*)d_in[2];
    const float* part_feats = (const float*)d_in[3];
    const float* Wg_w       = (const float*)d_in[4];
    const float* Wg_b       = (const float*)d_in[5];
    const float* Wq_w       = (const float*)d_in[6];
    const float* Wq_b       = (const float*)d_in[7];
    const float* Wk_w       = (const float*)d_in[8];
    const float* Wk_b       = (const float*)d_in[9];
    const float* conv_w     = (const float*)d_in[10];
    const float* conv_b     = (const float*)d_in[11];
    float* out = (float*)d_out;

    float *q, *k, *pw, *L;
    cudaGetSymbolAddress((void**)&q,  g_q);
    cudaGetSymbolAddress((void**)&k,  g_k);
    cudaGetSymbolAddress((void**)&pw, g_pw);
    cudaGetSymbolAddress((void**)&L,  g_L);

    const int SMG = 2 * (2 * 128 * 80 + 2 * 64 * 80);     // 61440
    const int SMP = (16 * 1024 + 16 * 64 + 16) * 4;       // 69696
    cudaFuncSetAttribute(tgemm64, cudaFuncAttributeMaxDynamicSharedMemorySize, SMG);
    cudaFuncSetAttribute(fused_ps, cudaFuncAttributeMaxDynamicSharedMemorySize, SMP);

    // q = box_feats @ Wq^T + Wq_b         M=2048 N=1024 K=1024
    tgemm64<<<dim3(16, 16, 1), 256, SMG>>>(
        box_feats, Wq_w, Wq_b, q, 1024, 1024, 1024, 1024,
        0, 0, 0, 0, 0, 0, 0, 1, 1.f);

    // k = part_feats @ Wk^T + Wk_b
    tgemm64<<<dim3(16, 16, 1), 256, SMG>>>(
        part_feats, Wk_w, Wk_b, k, 1024, 1024, 1024, 1024,
        0, 0, 0, 0, 0, 0, 0, 1, 1.f);

    // pwT = conv_w @ part_feats^T         M=1024 N=2048 K=1024  -> [GE, P]
    tgemm64<<<dim3(32, 8, 1), 256, SMG>>>(
        conv_w, part_feats, nullptr, pw, 1024, 1024, 1024, 2048,
        0, 0, 0, 0, 0, 0, 0, 1, 1.f);

    // att/16 into L: 32 batches (b,g): M=1024 N=1024 K=64
    tgemm64<<<dim3(16, 8, 32), 256, SMG>>>(
        q, k, nullptr, L, 64, 1024, 1024, 16384,
        1048576LL, 64LL, 1048576LL, 64LL,
        16777216LL, 1024LL, 0LL, 16, 1.f / 16.f);

    // L = softmax(L + log(att_weight)) fused
    fused_ps<<<dim3(1024, 2), 256, SMP>>>(rois, part_rois, Wg_w, Wg_b, L);

    // rel = sm @ pwT^T + conv_b: 32 batches: M=1024 N=64 K=1024
    tgemm64<<<dim3(1, 8, 32), 256, SMG>>>(
        L, pw, conv_b, out, 1024, 16384, 2048, 1024,
        16777216LL, 1024LL, 1024LL, 131072LL,
        1048576LL, 64LL, 64LL, 16, 1.f);
}